// round 1
// baseline (speedup 1.0000x reference)
#include <cuda_runtime.h>
#include <math.h>

// Problem constants
#define BSZ   2
#define NSEQ  2048
#define HN    8
#define HD    32
#define EMB   256
#define PDIM  12          // QP*3
#define DIMT  44          // 32 + 12
#define DIMP  48          // padded
#define NRAW  1056        // 256*3 + 96*3
#define CTXW  352         // 256 + 96

// Scratch (device globals; allocation-free rule)
__device__ float g_praw[BSZ * NSEQ * NRAW];                 // raw projections
__device__ float g_q[BSZ * HN * NSEQ * DIMP];               // scaled q|qp, padded 48
__device__ float g_k[BSZ * HN * NSEQ * DIMP];
__device__ float g_v[BSZ * HN * NSEQ * DIMP];
__device__ float g_kb[BSZ * HN * NSEQ];                     // -0.5*wc*kk column bias
__device__ float g_ctx[BSZ * NSEQ * CTXW];                  // attention output context

// ---------------------------------------------------------------------------
// Generic tiled fp32 GEMM: C[m, coff+n] = A[m,:K] @ W[:K, n] + bias[n]
// BM=64, BN=64, BK=16, 256 threads, 4x4 register tile.
// ---------------------------------------------------------------------------
__global__ __launch_bounds__(256)
void gemm_kernel(const float* __restrict__ A, const float* __restrict__ W,
                 const float* __restrict__ bias, float* __restrict__ C,
                 int M, int K, int Nw, int ldc, int coff) {
    __shared__ float As[16][68];
    __shared__ float Bs[16][68];
    const int m0 = blockIdx.y * 64;
    const int n0 = blockIdx.x * 64;
    const int t = threadIdx.x;

    const int arow = t >> 2;            // 0..63
    const int akg  = (t & 3) * 4;       // 0,4,8,12
    const int bk   = t >> 4;            // 0..15
    const int bn   = (t & 15) * 4;      // 0..60

    const int cx = (t & 15) * 4;        // col offset of 4x4 tile
    const int ry = (t >> 4) * 4;        // row offset of 4x4 tile

    float acc[4][4];
#pragma unroll
    for (int i = 0; i < 4; i++)
#pragma unroll
        for (int j = 0; j < 4; j++) acc[i][j] = 0.f;

    for (int k0 = 0; k0 < K; k0 += 16) {
        // A tile 64x16 (transposed into As[k][m])
        float4 a4 = *(const float4*)(A + (size_t)(m0 + arow) * K + k0 + akg);
        As[akg + 0][arow] = a4.x;
        As[akg + 1][arow] = a4.y;
        As[akg + 2][arow] = a4.z;
        As[akg + 3][arow] = a4.w;
        // B tile 16x64 with N guard
        {
            const float* wr = W + (size_t)(k0 + bk) * Nw;
            int gcol = n0 + bn;
            if (gcol + 3 < Nw) {
                float4 b4 = *(const float4*)(wr + gcol);
                Bs[bk][bn + 0] = b4.x;
                Bs[bk][bn + 1] = b4.y;
                Bs[bk][bn + 2] = b4.z;
                Bs[bk][bn + 3] = b4.w;
            } else {
#pragma unroll
                for (int i = 0; i < 4; i++)
                    Bs[bk][bn + i] = (gcol + i < Nw) ? wr[gcol + i] : 0.f;
            }
        }
        __syncthreads();
#pragma unroll
        for (int kk = 0; kk < 16; kk++) {
            float4 av = *(const float4*)&As[kk][ry];
            float4 bv = *(const float4*)&Bs[kk][cx];
            float aa[4] = {av.x, av.y, av.z, av.w};
            float bb[4] = {bv.x, bv.y, bv.z, bv.w};
#pragma unroll
            for (int i = 0; i < 4; i++)
#pragma unroll
                for (int j = 0; j < 4; j++)
                    acc[i][j] = fmaf(aa[i], bb[j], acc[i][j]);
        }
        __syncthreads();
    }
#pragma unroll
    for (int i = 0; i < 4; i++) {
        float* crow = C + (size_t)(m0 + ry + i) * ldc + coff;
#pragma unroll
        for (int j = 0; j < 4; j++) {
            int col = n0 + cx + j;
            if (col < Nw) crow[col] = acc[i][j] + bias[col];
        }
    }
}

// ---------------------------------------------------------------------------
// Transform: build scaled/padded Q,K,V (layout [b][h][pos][48]) + kb bias.
// One block per (b,pos), 128 threads.
// ---------------------------------------------------------------------------
__device__ __forceinline__ float softplusf(float x) {
    return (x > 20.f) ? x : log1pf(expf(x));
}

__global__ __launch_bounds__(128)
void transform_kernel(const float* __restrict__ coords,
                      const float* __restrict__ w_c,
                      const float* __restrict__ w_l) {
    __shared__ float row[NRAW];
    __shared__ float c3[3];
    __shared__ float wl[HN], wc[HN];
    const int blk = blockIdx.x;            // b*NSEQ + pos
    const int b = blk >> 11;               // /2048
    const int pos = blk & (NSEQ - 1);
    const int t = threadIdx.x;

    for (int i = t; i < NRAW; i += 128) row[i] = g_praw[(size_t)blk * NRAW + i];
    if (t < 3) c3[t] = coords[(size_t)blk * 3 + t];
    if (t < HN) { wl[t] = softplusf(w_l[t]); wc[t] = softplusf(w_c[t]); }
    __syncthreads();

    // kb = -0.5*wc*sum(kp^2); (qb cancels in softmax, skipped)
    if (t < HN) {
        int h = t;
        float s = 0.f;
#pragma unroll
        for (int e = 0; e < PDIM; e++) {
            float v = row[864 + h * PDIM + e] + c3[e % 3];
            s = fmaf(v, v, s);
        }
        g_kb[((size_t)(b * HN + h)) * NSEQ + pos] = -0.5f * wc[h] * s;
    }

    const float RS32 = 0.17677669529663688f;   // 1/sqrt(32)
    for (int idx = t; idx < HN * DIMP; idx += 128) {
        int h = idx / DIMP, d = idx % DIMP;
        size_t o = (((size_t)(b * HN + h)) * NSEQ + pos) * DIMP + d;
        float qv, kv, vv;
        if (d < HD) {
            qv = row[h * HD + d] * (wl[h] * RS32);
            kv = row[256 + h * HD + d];
            vv = row[512 + h * HD + d];
        } else if (d < DIMT) {
            int e = d - HD;
            float cc = c3[e % 3];
            qv = (row[768 + h * PDIM + e] + cc) * wc[h];
            kv = row[864 + h * PDIM + e] + cc;
            vv = row[960 + h * PDIM + e] + cc;
        } else {
            qv = kv = vv = 0.f;
        }
        g_q[o] = qv; g_k[o] = kv; g_v[o] = vv;
    }
}

// ---------------------------------------------------------------------------
// Attention: flash-style online softmax. Block = (64 i-rows, one (b,h)).
// Shared: Qs/Ks transposed [48][68], Vs [64][48], Ps [64 cols][68 rows].
// ---------------------------------------------------------------------------
#define SM_QS 0
#define SM_KS (48 * 68)
#define SM_VS (SM_KS + 48 * 68)
#define SM_PS (SM_VS + 64 * 48)
#define SM_KB (SM_PS + 64 * 68)
#define SM_MS (SM_KB + 64)
#define SM_LS (SM_MS + 64)
#define SM_FS (SM_LS + 64)
#define SM_TOT (SM_FS + 64)   // floats

__global__ __launch_bounds__(256)
void attn_kernel(const unsigned char* __restrict__ mask, float* __restrict__ ctx) {
    extern __shared__ float sm[];
    float* Qs = sm + SM_QS;
    float* Ks = sm + SM_KS;
    float* Vs = sm + SM_VS;
    float* Ps = sm + SM_PS;
    float* kbs = sm + SM_KB;
    float* m_s = sm + SM_MS;
    float* l_s = sm + SM_LS;
    float* fac_s = sm + SM_FS;

    const int i0 = blockIdx.x * 64;
    const int h = blockIdx.y;
    const int b = blockIdx.z;
    const int bh = b * HN + h;
    const float* Qg = g_q + (size_t)bh * NSEQ * DIMP;
    const float* Kg = g_k + (size_t)bh * NSEQ * DIMP;
    const float* Vg = g_v + (size_t)bh * NSEQ * DIMP;
    const int t = threadIdx.x;

    // load Q tile transposed
    for (int idx = t; idx < 64 * 12; idx += 256) {
        int r = idx / 12, dg = (idx % 12) * 4;
        float4 q4 = *(const float4*)(Qg + (size_t)(i0 + r) * DIMP + dg);
        Qs[(dg + 0) * 68 + r] = q4.x;
        Qs[(dg + 1) * 68 + r] = q4.y;
        Qs[(dg + 2) * 68 + r] = q4.z;
        Qs[(dg + 3) * 68 + r] = q4.w;
    }
    if (t < 64) { m_s[t] = -INFINITY; l_s[t] = 0.f; }

    // thread tiles
    const int rs = (t & 15) * 4, cs = (t >> 4) * 4;        // S compute: 4x4
    const int r0v = (t >> 4) * 4, c0v = (t & 15) * 3;      // P@V: 4 rows x 3 cols
    float acc[4][3];
#pragma unroll
    for (int i = 0; i < 4; i++)
#pragma unroll
        for (int j = 0; j < 3; j++) acc[i][j] = 0.f;

    __syncthreads();

    for (int j0 = 0; j0 < NSEQ; j0 += 64) {
        // load K (transposed) and V tiles
        for (int idx = t; idx < 64 * 12; idx += 256) {
            int r = idx / 12, dg = (idx % 12) * 4;
            float4 k4 = *(const float4*)(Kg + (size_t)(j0 + r) * DIMP + dg);
            Ks[(dg + 0) * 68 + r] = k4.x;
            Ks[(dg + 1) * 68 + r] = k4.y;
            Ks[(dg + 2) * 68 + r] = k4.z;
            Ks[(dg + 3) * 68 + r] = k4.w;
            float4 v4 = *(const float4*)(Vg + (size_t)(j0 + r) * DIMP + dg);
            *(float4*)(Vs + r * 48 + dg) = v4;
        }
        if (t < 64) kbs[t] = g_kb[(size_t)bh * NSEQ + j0 + t];
        __syncthreads();

        // S = Q'.K (44-dim dot, padded to 48)
        float s[4][4];
#pragma unroll
        for (int i = 0; i < 4; i++)
#pragma unroll
            for (int j = 0; j < 4; j++) s[i][j] = 0.f;
#pragma unroll 8
        for (int d = 0; d < DIMP; d++) {
            float4 q4 = *(const float4*)(Qs + d * 68 + rs);
            float4 k4 = *(const float4*)(Ks + d * 68 + cs);
            float qa[4] = {q4.x, q4.y, q4.z, q4.w};
            float ka[4] = {k4.x, k4.y, k4.z, k4.w};
#pragma unroll
            for (int i = 0; i < 4; i++)
#pragma unroll
                for (int j = 0; j < 4; j++)
                    s[i][j] = fmaf(qa[i], ka[j], s[i][j]);
        }
        // bias + mask, store transposed into Ps[col][row]
#pragma unroll
        for (int ri = 0; ri < 4; ri++) {
            int irow = rs + ri;
            const unsigned char* mp =
                mask + ((size_t)b * NSEQ + (i0 + irow)) * NSEQ + j0 + cs;
            uchar4 mv = *(const uchar4*)mp;
            float v0 = s[ri][0] + kbs[cs + 0];
            float v1 = s[ri][1] + kbs[cs + 1];
            float v2 = s[ri][2] + kbs[cs + 2];
            float v3 = s[ri][3] + kbs[cs + 3];
            if (mv.x) v0 = -INFINITY;
            if (mv.y) v1 = -INFINITY;
            if (mv.z) v2 = -INFINITY;
            if (mv.w) v3 = -INFINITY;
            Ps[(cs + 0) * 68 + irow] = v0;
            Ps[(cs + 1) * 68 + irow] = v1;
            Ps[(cs + 2) * 68 + irow] = v2;
            Ps[(cs + 3) * 68 + irow] = v3;
        }
        __syncthreads();

        // row stats: 4 threads per row
        {
            int r = t >> 2, p = t & 3;
            float mx = -INFINITY;
#pragma unroll
            for (int ss = 0; ss < 16; ss++)
                mx = fmaxf(mx, Ps[(p * 16 + ss) * 68 + r]);
            mx = fmaxf(mx, __shfl_xor_sync(0xffffffffu, mx, 1));
            mx = fmaxf(mx, __shfl_xor_sync(0xffffffffu, mx, 2));
            float mold = m_s[r];
            float mnew = fmaxf(mold, mx);
            float sum = 0.f;
#pragma unroll
            for (int ss = 0; ss < 16; ss++) {
                float* pp = &Ps[(p * 16 + ss) * 68 + r];
                float e = __expf(*pp - mnew);
                *pp = e;
                sum += e;
            }
            sum += __shfl_xor_sync(0xffffffffu, sum, 1);
            sum += __shfl_xor_sync(0xffffffffu, sum, 2);
            if (p == 0) {
                float f = __expf(mold - mnew);
                fac_s[r] = f;
                l_s[r] = l_s[r] * f + sum;
                m_s[r] = mnew;
            }
        }
        __syncthreads();

        // rescale and accumulate O += P @ V
        {
            float fr[4];
#pragma unroll
            for (int i = 0; i < 4; i++) fr[i] = fac_s[r0v + i];
#pragma unroll
            for (int i = 0; i < 4; i++)
#pragma unroll
                for (int j = 0; j < 3; j++) acc[i][j] *= fr[i];
        }
#pragma unroll 4
        for (int j = 0; j < 64; j++) {
            float4 p4 = *(const float4*)(Ps + j * 68 + r0v);
            float pa[4] = {p4.x, p4.y, p4.z, p4.w};
            const float* vr = Vs + j * 48 + c0v;
            float va[3] = {vr[0], vr[1], vr[2]};
#pragma unroll
            for (int i = 0; i < 4; i++)
#pragma unroll
                for (int c = 0; c < 3; c++)
                    acc[i][c] = fmaf(pa[i], va[c], acc[i][c]);
        }
        __syncthreads();
    }

    // normalize and write ctx
#pragma unroll
    for (int ri = 0; ri < 4; ri++) {
        int irow = r0v + ri;
        float inv = 1.f / l_s[irow];
        size_t ob = ((size_t)b * NSEQ + (i0 + irow)) * CTXW;
#pragma unroll
        for (int ci = 0; ci < 3; ci++) {
            int c = c0v + ci;
            if (c >= DIMT) continue;
            float o = acc[ri][ci] * inv;
            if (c < HD)
                ctx[ob + h * HD + c] = o;
            else
                ctx[ob + 256 + h * PDIM + (c - HD)] = o;
        }
    }
}

// ---------------------------------------------------------------------------
extern "C" void kernel_launch(void* const* d_in, const int* in_sizes, int n_in,
                              void* d_out, int out_size) {
    const float* feat   = (const float*)d_in[0];
    const float* coords = (const float*)d_in[1];
    const unsigned char* mask = (const unsigned char*)d_in[2];
    const float* Wq  = (const float*)d_in[3];
    const float* bq  = (const float*)d_in[4];
    const float* Wk  = (const float*)d_in[5];
    const float* bk  = (const float*)d_in[6];
    const float* Wv  = (const float*)d_in[7];
    const float* bv  = (const float*)d_in[8];
    const float* Wqp = (const float*)d_in[9];
    const float* bqp = (const float*)d_in[10];
    const float* Wkp = (const float*)d_in[11];
    const float* bkp = (const float*)d_in[12];
    const float* Wvp = (const float*)d_in[13];
    const float* bvp = (const float*)d_in[14];
    const float* Wo  = (const float*)d_in[15];
    const float* bo  = (const float*)d_in[16];
    const float* w_c = (const float*)d_in[17];
    const float* w_l = (const float*)d_in[18];
    float* out = (float*)d_out;

    void* p;
    cudaGetSymbolAddress(&p, g_praw);  float* praw = (float*)p;
    cudaGetSymbolAddress(&p, g_ctx);   float* ctx  = (float*)p;

    const int M = BSZ * NSEQ;   // 4096
    // projections into praw
    gemm_kernel<<<dim3(4, M / 64), 256>>>(feat, Wq,  bq,  praw, M, EMB, 256, NRAW, 0);
    gemm_kernel<<<dim3(4, M / 64), 256>>>(feat, Wk,  bk,  praw, M, EMB, 256, NRAW, 256);
    gemm_kernel<<<dim3(4, M / 64), 256>>>(feat, Wv,  bv,  praw, M, EMB, 256, NRAW, 512);
    gemm_kernel<<<dim3(2, M / 64), 256>>>(feat, Wqp, bqp, praw, M, EMB, 96,  NRAW, 768);
    gemm_kernel<<<dim3(2, M / 64), 256>>>(feat, Wkp, bkp, praw, M, EMB, 96,  NRAW, 864);
    gemm_kernel<<<dim3(2, M / 64), 256>>>(feat, Wvp, bvp, praw, M, EMB, 96,  NRAW, 960);

    transform_kernel<<<M, 128>>>(coords, w_c, w_l);

    cudaFuncSetAttribute(attn_kernel, cudaFuncAttributeMaxDynamicSharedMemorySize,
                         SM_TOT * (int)sizeof(float));
    attn_kernel<<<dim3(NSEQ / 64, HN, BSZ), 256, SM_TOT * (int)sizeof(float)>>>(mask, ctx);

    // output projection: ctx[4096,352] @ Wo[352,256] + bo
    gemm_kernel<<<dim3(4, M / 64), 256>>>(ctx, Wo, bo, out, M, CTXW, 256, 256, 0);
}

// round 2
// speedup vs baseline: 1.1380x; 1.1380x over previous
#include <cuda_runtime.h>
#include <math.h>

// Problem constants
#define BSZ   2
#define NSEQ  2048
#define HN    8
#define HD    32
#define EMB   256
#define PDIM  12          // QP*3
#define DIMT  44          // 32 + 12
#define DIMP  48          // padded
#define NRAW  1056        // 256*3 + 96*3
#define CTXW  352         // 256 + 96

typedef unsigned long long u64;

// ---- packed fp32x2 helpers (FFMA2 path: ptxas never emits these from C++) ----
__device__ __forceinline__ u64 pk2(float lo, float hi) {
    u64 r; asm("mov.b64 %0, {%1, %2};" : "=l"(r) : "f"(lo), "f"(hi)); return r;
}
__device__ __forceinline__ u64 bc2(float x) { return pk2(x, x); }
__device__ __forceinline__ void fma2(u64& d, u64 a, u64 b) {
    asm("fma.rn.f32x2 %0, %1, %2, %0;" : "+l"(d) : "l"(a), "l"(b));
}
__device__ __forceinline__ void add2(u64& d, u64 a) {
    asm("add.rn.f32x2 %0, %0, %1;" : "+l"(d) : "l"(a));
}
__device__ __forceinline__ void mul2(u64& d, u64 a) {
    asm("mul.rn.f32x2 %0, %0, %1;" : "+l"(d) : "l"(a));
}
__device__ __forceinline__ void upk2(u64 v, float& lo, float& hi) {
    asm("mov.b64 {%0, %1}, %2;" : "=f"(lo), "=f"(hi) : "l"(v));
}

// Scratch (device globals; allocation-free rule)
__device__ float g_praw[BSZ * NSEQ * NRAW];                 // raw projections
__device__ float g_q[BSZ * HN * NSEQ * DIMP];               // scaled q|qp, padded 48
__device__ float g_k[BSZ * HN * NSEQ * DIMP];
__device__ float g_v[BSZ * HN * NSEQ * DIMP];
__device__ float g_kb[BSZ * HN * NSEQ];                     // -0.5*wc*kk column bias
__device__ float g_ctx[BSZ * NSEQ * CTXW];                  // attention output context

// ---------------------------------------------------------------------------
// Generic tiled fp32 GEMM with packed FFMA2 inner loop.
// C[m, coff+n] = A[m,:K] @ W[:K, n] + bias[n]
// ---------------------------------------------------------------------------
__global__ __launch_bounds__(256)
void gemm_kernel(const float* __restrict__ A, const float* __restrict__ W,
                 const float* __restrict__ bias, float* __restrict__ C,
                 int M, int K, int Nw, int ldc, int coff) {
    __shared__ float As[16][68];
    __shared__ float Bs[16][68];
    const int m0 = blockIdx.y * 64;
    const int n0 = blockIdx.x * 64;
    const int t = threadIdx.x;

    const int arow = t >> 2;            // 0..63
    const int akg  = (t & 3) * 4;       // 0,4,8,12
    const int bk   = t >> 4;            // 0..15
    const int bn   = (t & 15) * 4;      // 0..60

    const int cx = (t & 15) * 4;        // col offset of 4x4 tile
    const int ry = (t >> 4) * 4;        // row offset of 4x4 tile

    u64 acc2[4][2];
#pragma unroll
    for (int i = 0; i < 4; i++) { acc2[i][0] = 0ull; acc2[i][1] = 0ull; }

    for (int k0 = 0; k0 < K; k0 += 16) {
        float4 a4 = *(const float4*)(A + (size_t)(m0 + arow) * K + k0 + akg);
        As[akg + 0][arow] = a4.x;
        As[akg + 1][arow] = a4.y;
        As[akg + 2][arow] = a4.z;
        As[akg + 3][arow] = a4.w;
        {
            const float* wr = W + (size_t)(k0 + bk) * Nw;
            int gcol = n0 + bn;
            if (gcol + 3 < Nw) {
                float4 b4 = *(const float4*)(wr + gcol);
                Bs[bk][bn + 0] = b4.x;
                Bs[bk][bn + 1] = b4.y;
                Bs[bk][bn + 2] = b4.z;
                Bs[bk][bn + 3] = b4.w;
            } else {
#pragma unroll
                for (int i = 0; i < 4; i++)
                    Bs[bk][bn + i] = (gcol + i < Nw) ? wr[gcol + i] : 0.f;
            }
        }
        __syncthreads();
#pragma unroll
        for (int kk = 0; kk < 16; kk++) {
            float4 av = *(const float4*)&As[kk][ry];
            ulonglong2 bv = *(const ulonglong2*)&Bs[kk][cx];
            u64 ab0 = bc2(av.x), ab1 = bc2(av.y), ab2 = bc2(av.z), ab3 = bc2(av.w);
            fma2(acc2[0][0], ab0, bv.x); fma2(acc2[0][1], ab0, bv.y);
            fma2(acc2[1][0], ab1, bv.x); fma2(acc2[1][1], ab1, bv.y);
            fma2(acc2[2][0], ab2, bv.x); fma2(acc2[2][1], ab2, bv.y);
            fma2(acc2[3][0], ab3, bv.x); fma2(acc2[3][1], ab3, bv.y);
        }
        __syncthreads();
    }
#pragma unroll
    for (int i = 0; i < 4; i++) {
        float c0, c1, c2, c3;
        upk2(acc2[i][0], c0, c1);
        upk2(acc2[i][1], c2, c3);
        float cc[4] = {c0, c1, c2, c3};
        float* crow = C + (size_t)(m0 + ry + i) * ldc + coff;
#pragma unroll
        for (int j = 0; j < 4; j++) {
            int col = n0 + cx + j;
            if (col < Nw) crow[col] = cc[j] + bias[col];
        }
    }
}

// ---------------------------------------------------------------------------
// Transform: build scaled/padded Q,K,V (layout [b][h][pos][48]) + kb bias.
// ---------------------------------------------------------------------------
__device__ __forceinline__ float softplusf(float x) {
    return (x > 20.f) ? x : log1pf(expf(x));
}

__global__ __launch_bounds__(128)
void transform_kernel(const float* __restrict__ coords,
                      const float* __restrict__ w_c,
                      const float* __restrict__ w_l) {
    __shared__ float row[NRAW];
    __shared__ float c3[3];
    __shared__ float wl[HN], wc[HN];
    const int blk = blockIdx.x;            // b*NSEQ + pos
    const int b = blk >> 11;               // /2048
    const int pos = blk & (NSEQ - 1);
    const int t = threadIdx.x;

    for (int i = t; i < NRAW; i += 128) row[i] = g_praw[(size_t)blk * NRAW + i];
    if (t < 3) c3[t] = coords[(size_t)blk * 3 + t];
    if (t < HN) { wl[t] = softplusf(w_l[t]); wc[t] = softplusf(w_c[t]); }
    __syncthreads();

    if (t < HN) {
        int h = t;
        float s = 0.f;
#pragma unroll
        for (int e = 0; e < PDIM; e++) {
            float v = row[864 + h * PDIM + e] + c3[e % 3];
            s = fmaf(v, v, s);
        }
        g_kb[((size_t)(b * HN + h)) * NSEQ + pos] = -0.5f * wc[h] * s;
    }

    const float RS32 = 0.17677669529663688f;   // 1/sqrt(32)
    for (int idx = t; idx < HN * DIMP; idx += 128) {
        int h = idx / DIMP, d = idx % DIMP;
        size_t o = (((size_t)(b * HN + h)) * NSEQ + pos) * DIMP + d;
        float qv, kv, vv;
        if (d < HD) {
            qv = row[h * HD + d] * (wl[h] * RS32);
            kv = row[256 + h * HD + d];
            vv = row[512 + h * HD + d];
        } else if (d < DIMT) {
            int e = d - HD;
            float cc = c3[e % 3];
            qv = (row[768 + h * PDIM + e] + cc) * wc[h];
            kv = row[864 + h * PDIM + e] + cc;
            vv = row[960 + h * PDIM + e] + cc;
        } else {
            qv = kv = vv = 0.f;
        }
        g_q[o] = qv; g_k[o] = kv; g_v[o] = vv;
    }
}

// ---------------------------------------------------------------------------
// Attention: flash-style online softmax with packed FFMA2 math.
// Block = (64 i-rows, one (b,h)), 256 threads.
// ---------------------------------------------------------------------------
#define SM_QS 0
#define SM_KS (48 * 68)
#define SM_VS (SM_KS + 48 * 68)
#define SM_PS (SM_VS + 64 * 48)
#define SM_KB (SM_PS + 64 * 68)
#define SM_MS (SM_KB + 64)
#define SM_LS (SM_MS + 64)
#define SM_FS (SM_LS + 64)
#define SM_TOT (SM_FS + 64)   // floats

__global__ __launch_bounds__(256)
void attn_kernel(const unsigned char* __restrict__ mask, float* __restrict__ ctx) {
    extern __shared__ float sm[];
    float* Qs = sm + SM_QS;
    float* Ks = sm + SM_KS;
    float* Vs = sm + SM_VS;
    float* Ps = sm + SM_PS;
    float* kbs = sm + SM_KB;
    float* m_s = sm + SM_MS;
    float* l_s = sm + SM_LS;
    float* fac_s = sm + SM_FS;

    const int i0 = blockIdx.x * 64;
    const int h = blockIdx.y;
    const int b = blockIdx.z;
    const int bh = b * HN + h;
    const float* Qg = g_q + (size_t)bh * NSEQ * DIMP;
    const float* Kg = g_k + (size_t)bh * NSEQ * DIMP;
    const float* Vg = g_v + (size_t)bh * NSEQ * DIMP;
    const int t = threadIdx.x;

    // load Q tile transposed
    for (int idx = t; idx < 64 * 12; idx += 256) {
        int r = idx / 12, dg = (idx % 12) * 4;
        float4 q4 = *(const float4*)(Qg + (size_t)(i0 + r) * DIMP + dg);
        Qs[(dg + 0) * 68 + r] = q4.x;
        Qs[(dg + 1) * 68 + r] = q4.y;
        Qs[(dg + 2) * 68 + r] = q4.z;
        Qs[(dg + 3) * 68 + r] = q4.w;
    }
    if (t < 64) { m_s[t] = -INFINITY; l_s[t] = 0.f; }

    // thread tiles
    const int rs = (t & 15) * 4, cs = (t >> 4) * 4;        // S compute: 4x4
    const int r0v = (t >> 4) * 4, c0v = (t & 15) * 3;      // P@V: 4 rows x 3 cols
    u64 acc2[2][3];
#pragma unroll
    for (int i = 0; i < 2; i++)
#pragma unroll
        for (int j = 0; j < 3; j++) acc2[i][j] = 0ull;

    __syncthreads();

    for (int j0 = 0; j0 < NSEQ; j0 += 64) {
        // load K (transposed) and V tiles
        for (int idx = t; idx < 64 * 12; idx += 256) {
            int r = idx / 12, dg = (idx % 12) * 4;
            float4 k4 = *(const float4*)(Kg + (size_t)(j0 + r) * DIMP + dg);
            Ks[(dg + 0) * 68 + r] = k4.x;
            Ks[(dg + 1) * 68 + r] = k4.y;
            Ks[(dg + 2) * 68 + r] = k4.z;
            Ks[(dg + 3) * 68 + r] = k4.w;
            float4 v4 = *(const float4*)(Vg + (size_t)(j0 + r) * DIMP + dg);
            *(float4*)(Vs + r * 48 + dg) = v4;
        }
        if (t < 64) kbs[t] = g_kb[(size_t)bh * NSEQ + j0 + t];
        __syncthreads();

        // S = Q'.K  (packed over j pairs)
        u64 s2[4][2];
#pragma unroll
        for (int i = 0; i < 4; i++) { s2[i][0] = 0ull; s2[i][1] = 0ull; }
#pragma unroll 8
        for (int d = 0; d < DIMP; d++) {
            float4 q4 = *(const float4*)(Qs + d * 68 + rs);
            ulonglong2 kk = *(const ulonglong2*)(Ks + d * 68 + cs);
            u64 qb0 = bc2(q4.x), qb1 = bc2(q4.y), qb2 = bc2(q4.z), qb3 = bc2(q4.w);
            fma2(s2[0][0], qb0, kk.x); fma2(s2[0][1], qb0, kk.y);
            fma2(s2[1][0], qb1, kk.x); fma2(s2[1][1], qb1, kk.y);
            fma2(s2[2][0], qb2, kk.x); fma2(s2[2][1], qb2, kk.y);
            fma2(s2[3][0], qb3, kk.x); fma2(s2[3][1], qb3, kk.y);
        }
        // column bias (packed) then unpack + mask + store transposed Ps[col][row]
        {
            ulonglong2 kbp = *(const ulonglong2*)(kbs + cs);
#pragma unroll
            for (int i = 0; i < 4; i++) { add2(s2[i][0], kbp.x); add2(s2[i][1], kbp.y); }
        }
#pragma unroll
        for (int ri = 0; ri < 4; ri++) {
            int irow = rs + ri;
            const unsigned char* mp =
                mask + ((size_t)b * NSEQ + (i0 + irow)) * NSEQ + j0 + cs;
            uchar4 mv = *(const uchar4*)mp;
            float v0, v1, v2, v3;
            upk2(s2[ri][0], v0, v1);
            upk2(s2[ri][1], v2, v3);
            if (mv.x) v0 = -INFINITY;
            if (mv.y) v1 = -INFINITY;
            if (mv.z) v2 = -INFINITY;
            if (mv.w) v3 = -INFINITY;
            Ps[(cs + 0) * 68 + irow] = v0;
            Ps[(cs + 1) * 68 + irow] = v1;
            Ps[(cs + 2) * 68 + irow] = v2;
            Ps[(cs + 3) * 68 + irow] = v3;
        }
        __syncthreads();

        // row stats: 4 threads per row
        {
            int r = t >> 2, p = t & 3;
            float mx = -INFINITY;
#pragma unroll
            for (int ss = 0; ss < 16; ss++)
                mx = fmaxf(mx, Ps[(p * 16 + ss) * 68 + r]);
            mx = fmaxf(mx, __shfl_xor_sync(0xffffffffu, mx, 1));
            mx = fmaxf(mx, __shfl_xor_sync(0xffffffffu, mx, 2));
            float mold = m_s[r];
            float mnew = fmaxf(mold, mx);
            float sum = 0.f;
#pragma unroll
            for (int ss = 0; ss < 16; ss++) {
                float* pp = &Ps[(p * 16 + ss) * 68 + r];
                float e = __expf(*pp - mnew);
                *pp = e;
                sum += e;
            }
            sum += __shfl_xor_sync(0xffffffffu, sum, 1);
            sum += __shfl_xor_sync(0xffffffffu, sum, 2);
            if (p == 0) {
                float f = __expf(mold - mnew);
                fac_s[r] = f;
                l_s[r] = l_s[r] * f + sum;
                m_s[r] = mnew;
            }
        }
        __syncthreads();

        // rescale and accumulate O += P @ V (packed over i pairs)
        {
            u64 f0 = pk2(fac_s[r0v + 0], fac_s[r0v + 1]);
            u64 f1 = pk2(fac_s[r0v + 2], fac_s[r0v + 3]);
#pragma unroll
            for (int j = 0; j < 3; j++) { mul2(acc2[0][j], f0); mul2(acc2[1][j], f1); }
        }
#pragma unroll 4
        for (int j = 0; j < 64; j++) {
            ulonglong2 pp = *(const ulonglong2*)(Ps + j * 68 + r0v);
            const float* vr = Vs + j * 48 + c0v;
            u64 vb0 = bc2(vr[0]), vb1 = bc2(vr[1]), vb2 = bc2(vr[2]);
            fma2(acc2[0][0], pp.x, vb0); fma2(acc2[1][0], pp.y, vb0);
            fma2(acc2[0][1], pp.x, vb1); fma2(acc2[1][1], pp.y, vb1);
            fma2(acc2[0][2], pp.x, vb2); fma2(acc2[1][2], pp.y, vb2);
        }
        __syncthreads();
    }

    // normalize and write ctx
    float accf[4][3];
#pragma unroll
    for (int j = 0; j < 3; j++) {
        upk2(acc2[0][j], accf[0][j], accf[1][j]);
        upk2(acc2[1][j], accf[2][j], accf[3][j]);
    }
#pragma unroll
    for (int ri = 0; ri < 4; ri++) {
        int irow = r0v + ri;
        float inv = 1.f / l_s[irow];
        size_t ob = ((size_t)b * NSEQ + (i0 + irow)) * CTXW;
#pragma unroll
        for (int ci = 0; ci < 3; ci++) {
            int c = c0v + ci;
            if (c >= DIMT) continue;
            float o = accf[ri][ci] * inv;
            if (c < HD)
                ctx[ob + h * HD + c] = o;
            else
                ctx[ob + 256 + h * PDIM + (c - HD)] = o;
        }
    }
}

// ---------------------------------------------------------------------------
extern "C" void kernel_launch(void* const* d_in, const int* in_sizes, int n_in,
                              void* d_out, int out_size) {
    const float* feat   = (const float*)d_in[0];
    const float* coords = (const float*)d_in[1];
    const unsigned char* mask = (const unsigned char*)d_in[2];
    const float* Wq  = (const float*)d_in[3];
    const float* bq  = (const float*)d_in[4];
    const float* Wk  = (const float*)d_in[5];
    const float* bk  = (const float*)d_in[6];
    const float* Wv  = (const float*)d_in[7];
    const float* bv  = (const float*)d_in[8];
    const float* Wqp = (const float*)d_in[9];
    const float* bqp = (const float*)d_in[10];
    const float* Wkp = (const float*)d_in[11];
    const float* bkp = (const float*)d_in[12];
    const float* Wvp = (const float*)d_in[13];
    const float* bvp = (const float*)d_in[14];
    const float* Wo  = (const float*)d_in[15];
    const float* bo  = (const float*)d_in[16];
    const float* w_c = (const float*)d_in[17];
    const float* w_l = (const float*)d_in[18];
    float* out = (float*)d_out;

    void* p;
    cudaGetSymbolAddress(&p, g_praw);  float* praw = (float*)p;
    cudaGetSymbolAddress(&p, g_ctx);   float* ctx  = (float*)p;

    const int M = BSZ * NSEQ;   // 4096
    gemm_kernel<<<dim3(4, M / 64), 256>>>(feat, Wq,  bq,  praw, M, EMB, 256, NRAW, 0);
    gemm_kernel<<<dim3(4, M / 64), 256>>>(feat, Wk,  bk,  praw, M, EMB, 256, NRAW, 256);
    gemm_kernel<<<dim3(4, M / 64), 256>>>(feat, Wv,  bv,  praw, M, EMB, 256, NRAW, 512);
    gemm_kernel<<<dim3(2, M / 64), 256>>>(feat, Wqp, bqp, praw, M, EMB, 96,  NRAW, 768);
    gemm_kernel<<<dim3(2, M / 64), 256>>>(feat, Wkp, bkp, praw, M, EMB, 96,  NRAW, 864);
    gemm_kernel<<<dim3(2, M / 64), 256>>>(feat, Wvp, bvp, praw, M, EMB, 96,  NRAW, 960);

    transform_kernel<<<M, 128>>>(coords, w_c, w_l);

    cudaFuncSetAttribute(attn_kernel, cudaFuncAttributeMaxDynamicSharedMemorySize,
                         SM_TOT * (int)sizeof(float));
    attn_kernel<<<dim3(NSEQ / 64, HN, BSZ), 256, SM_TOT * (int)sizeof(float)>>>(mask, ctx);

    gemm_kernel<<<dim3(4, M / 64), 256>>>(ctx, Wo, bo, out, M, CTXW, 256, 256, 0);
}

// round 3
// speedup vs baseline: 1.1942x; 1.0493x over previous
#include <cuda_runtime.h>
#include <math.h>

// Problem constants
#define BSZ   2
#define NSEQ  2048
#define HN    8
#define HD    32
#define EMB   256
#define PDIM  12          // QP*3
#define DIMT  44          // 32 + 12
#define DIMP  48          // padded
#define NRAW  1056        // 256*3 + 96*3
#define CTXW  352         // 256 + 96

typedef unsigned long long u64;

// ---- packed fp32x2 helpers (FFMA2: ptxas never emits from C++) ----
__device__ __forceinline__ u64 pk2(float lo, float hi) {
    u64 r; asm("mov.b64 %0, {%1, %2};" : "=l"(r) : "f"(lo), "f"(hi)); return r;
}
__device__ __forceinline__ u64 bc2(float x) { return pk2(x, x); }
__device__ __forceinline__ void fma2(u64& d, u64 a, u64 b) {
    asm("fma.rn.f32x2 %0, %1, %2, %0;" : "+l"(d) : "l"(a), "l"(b));
}
__device__ __forceinline__ void add2(u64& d, u64 a) {
    asm("add.rn.f32x2 %0, %0, %1;" : "+l"(d) : "l"(a));
}
__device__ __forceinline__ void mul2(u64& d, u64 a) {
    asm("mul.rn.f32x2 %0, %0, %1;" : "+l"(d) : "l"(a));
}
__device__ __forceinline__ void upk2(u64 v, float& lo, float& hi) {
    asm("mov.b64 {%0, %1}, %2;" : "=f"(lo), "=f"(hi) : "l"(v));
}

// Scratch (device globals; allocation-free rule)
__device__ float g_praw[BSZ * NSEQ * NRAW];
__device__ float g_q[BSZ * HN * NSEQ * DIMP];
__device__ float g_k[BSZ * HN * NSEQ * DIMP];
__device__ float g_v[BSZ * HN * NSEQ * DIMP];
__device__ float g_kb[BSZ * HN * NSEQ];
__device__ float g_ctx[BSZ * NSEQ * CTXW];

// ---------------------------------------------------------------------------
// Shared GEMM tile body: C[m, coff+n] = A[m,:K256] @ W[:,n] + bias[n]
// BM=64, BN=64, BK=16, 256 threads, 4x4 tile via FFMA2.
// ---------------------------------------------------------------------------
__device__ __forceinline__
void gemm_body(const float* __restrict__ A, const float* __restrict__ W,
               const float* __restrict__ bias, float* __restrict__ C,
               int K, int Nw, int ldc, int coff, int m0, int n0) {
    __shared__ float As[16][68];
    __shared__ float Bs[16][68];
    const int t = threadIdx.x;
    const int arow = t >> 2;
    const int akg  = (t & 3) * 4;
    const int bk   = t >> 4;
    const int bn   = (t & 15) * 4;
    const int cx = (t & 15) * 4;
    const int ry = (t >> 4) * 4;

    u64 acc2[4][2];
#pragma unroll
    for (int i = 0; i < 4; i++) { acc2[i][0] = 0ull; acc2[i][1] = 0ull; }

    for (int k0 = 0; k0 < K; k0 += 16) {
        float4 a4 = *(const float4*)(A + (size_t)(m0 + arow) * K + k0 + akg);
        As[akg + 0][arow] = a4.x;
        As[akg + 1][arow] = a4.y;
        As[akg + 2][arow] = a4.z;
        As[akg + 3][arow] = a4.w;
        {
            const float* wr = W + (size_t)(k0 + bk) * Nw;
            int gcol = n0 + bn;
            if (gcol + 3 < Nw) {
                float4 b4 = *(const float4*)(wr + gcol);
                Bs[bk][bn + 0] = b4.x;
                Bs[bk][bn + 1] = b4.y;
                Bs[bk][bn + 2] = b4.z;
                Bs[bk][bn + 3] = b4.w;
            } else {
#pragma unroll
                for (int i = 0; i < 4; i++)
                    Bs[bk][bn + i] = (gcol + i < Nw) ? wr[gcol + i] : 0.f;
            }
        }
        __syncthreads();
#pragma unroll
        for (int kk = 0; kk < 16; kk++) {
            float4 av = *(const float4*)&As[kk][ry];
            ulonglong2 bv = *(const ulonglong2*)&Bs[kk][cx];
            u64 ab0 = bc2(av.x), ab1 = bc2(av.y), ab2 = bc2(av.z), ab3 = bc2(av.w);
            fma2(acc2[0][0], ab0, bv.x); fma2(acc2[0][1], ab0, bv.y);
            fma2(acc2[1][0], ab1, bv.x); fma2(acc2[1][1], ab1, bv.y);
            fma2(acc2[2][0], ab2, bv.x); fma2(acc2[2][1], ab2, bv.y);
            fma2(acc2[3][0], ab3, bv.x); fma2(acc2[3][1], ab3, bv.y);
        }
        __syncthreads();
    }
#pragma unroll
    for (int i = 0; i < 4; i++) {
        float c0, c1, c2, c3;
        upk2(acc2[i][0], c0, c1);
        upk2(acc2[i][1], c2, c3);
        float cc[4] = {c0, c1, c2, c3};
        float* crow = C + (size_t)(m0 + ry + i) * ldc + coff;
#pragma unroll
        for (int j = 0; j < 4; j++) {
            int col = n0 + cx + j;
            if (col < Nw) crow[col] = cc[j] + bias[col];
        }
    }
}

// Merged projection GEMM: 6 matrices in one launch.
struct ProjArgs {
    const float* W[6];
    const float* bias[6];
};

__global__ __launch_bounds__(256)
void proj_kernel(const float* __restrict__ A, ProjArgs pa, float* __restrict__ C) {
    // tiles per matrix: 4,4,4,2,2,2 (Nw 256,256,256,96,96,96)
    const int bx = blockIdx.x;
    int g, n0;
    if (bx < 12) { g = bx >> 2; n0 = (bx & 3) * 64; }
    else         { g = 3 + ((bx - 12) >> 1); n0 = ((bx - 12) & 1) * 64; }
    const int nw   = (g < 3) ? 256 : 96;
    const int coff = (g < 3) ? g * 256 : 768 + (g - 3) * 96;
    gemm_body(A, pa.W[g], pa.bias[g], C, EMB, nw, NRAW, coff, blockIdx.y * 64, n0);
}

__global__ __launch_bounds__(256)
void gemm_kernel(const float* __restrict__ A, const float* __restrict__ W,
                 const float* __restrict__ bias, float* __restrict__ C,
                 int K, int Nw, int ldc) {
    gemm_body(A, W, bias, C, K, Nw, ldc, 0, blockIdx.y * 64, blockIdx.x * 64);
}

// ---------------------------------------------------------------------------
// Transform: build scaled/padded Q,K,V (layout [b][h][pos][48]) + kb bias.
// ---------------------------------------------------------------------------
__device__ __forceinline__ float softplusf(float x) {
    return (x > 20.f) ? x : log1pf(expf(x));
}

__global__ __launch_bounds__(128)
void transform_kernel(const float* __restrict__ coords,
                      const float* __restrict__ w_c,
                      const float* __restrict__ w_l) {
    __shared__ float row[NRAW];
    __shared__ float c3[3];
    __shared__ float wl[HN], wc[HN];
    const int blk = blockIdx.x;
    const int b = blk >> 11;
    const int pos = blk & (NSEQ - 1);
    const int t = threadIdx.x;

    for (int i = t; i < NRAW; i += 128) row[i] = g_praw[(size_t)blk * NRAW + i];
    if (t < 3) c3[t] = coords[(size_t)blk * 3 + t];
    if (t < HN) { wl[t] = softplusf(w_l[t]); wc[t] = softplusf(w_c[t]); }
    __syncthreads();

    if (t < HN) {
        int h = t;
        float s = 0.f;
#pragma unroll
        for (int e = 0; e < PDIM; e++) {
            float v = row[864 + h * PDIM + e] + c3[e % 3];
            s = fmaf(v, v, s);
        }
        g_kb[((size_t)(b * HN + h)) * NSEQ + pos] = -0.5f * wc[h] * s;
    }

    const float RS32 = 0.17677669529663688f;
    for (int idx = t; idx < HN * DIMP; idx += 128) {
        int h = idx / DIMP, d = idx % DIMP;
        size_t o = (((size_t)(b * HN + h)) * NSEQ + pos) * DIMP + d;
        float qv, kv, vv;
        if (d < HD) {
            qv = row[h * HD + d] * (wl[h] * RS32);
            kv = row[256 + h * HD + d];
            vv = row[512 + h * HD + d];
        } else if (d < DIMT) {
            int e = d - HD;
            float cc = c3[e % 3];
            qv = (row[768 + h * PDIM + e] + cc) * wc[h];
            kv = row[864 + h * PDIM + e] + cc;
            vv = row[960 + h * PDIM + e] + cc;
        } else {
            qv = kv = vv = 0.f;
        }
        g_q[o] = qv; g_k[o] = kv; g_v[o] = vv;
    }
}

// ---------------------------------------------------------------------------
// Attention: flash online softmax; register stats via half-warp shuffles;
// double-buffered V; 2 syncthreads/tile.
// Row groups owned by half-warps: rs=(t>>4)*4; S cols cs=(t&15)*4.
// ---------------------------------------------------------------------------
#define ATT_SMEM ((48*68) + (48*68) + 2*(64*48) + (64*68))   // 17024 floats

__global__ __launch_bounds__(256, 3)
void attn_kernel(const unsigned char* __restrict__ mask, float* __restrict__ ctx) {
    extern __shared__ float sm[];
    float* Qs  = sm;                 // [48][68] transposed
    float* Ks  = Qs + 48 * 68;       // [48][68] transposed
    float* Vb0 = Ks + 48 * 68;       // [64][48]
    float* Vb1 = Vb0 + 64 * 48;      // [64][48]
    float* Ps  = Vb1 + 64 * 48;      // [64 cols][68] (col-major, exp'd P)

    const int i0 = blockIdx.x * 64;
    const int h = blockIdx.y;
    const int b = blockIdx.z;
    const int bh = b * HN + h;
    const float* Qg = g_q + (size_t)bh * NSEQ * DIMP;
    const float* Kg = g_k + (size_t)bh * NSEQ * DIMP;
    const float* Vg = g_v + (size_t)bh * NSEQ * DIMP;
    const float* kbg = g_kb + (size_t)bh * NSEQ;

    const int t = threadIdx.x;
    const int rs  = (t >> 4) * 4;   // 4 rows (half-warp shared)
    const int cs  = (t & 15) * 4;   // 4 S-cols
    const int c0v = (t & 15) * 3;   // 3 V-cols

    // load Q tile transposed
    for (int idx = t; idx < 64 * 12; idx += 256) {
        int r = idx / 12, dg = (idx % 12) * 4;
        float4 q4 = *(const float4*)(Qg + (size_t)(i0 + r) * DIMP + dg);
        Qs[(dg + 0) * 68 + r] = q4.x;
        Qs[(dg + 1) * 68 + r] = q4.y;
        Qs[(dg + 2) * 68 + r] = q4.z;
        Qs[(dg + 3) * 68 + r] = q4.w;
    }

    float mrow[4], lrow[4];
#pragma unroll
    for (int i = 0; i < 4; i++) { mrow[i] = -INFINITY; lrow[i] = 0.f; }
    u64 acc2[2][3];
#pragma unroll
    for (int i = 0; i < 2; i++)
#pragma unroll
        for (int j = 0; j < 3; j++) acc2[i][j] = 0ull;

    int buf = 0;
    for (int j0 = 0; j0 < NSEQ; j0 += 64, buf ^= 1) {
        float* Vs = buf ? Vb1 : Vb0;
        // load K transposed + V
        for (int idx = t; idx < 64 * 12; idx += 256) {
            int r = idx / 12, dg = (idx % 12) * 4;
            float4 k4 = *(const float4*)(Kg + (size_t)(j0 + r) * DIMP + dg);
            Ks[(dg + 0) * 68 + r] = k4.x;
            Ks[(dg + 1) * 68 + r] = k4.y;
            Ks[(dg + 2) * 68 + r] = k4.z;
            Ks[(dg + 3) * 68 + r] = k4.w;
            float4 v4 = *(const float4*)(Vg + (size_t)(j0 + r) * DIMP + dg);
            *(float4*)(Vs + r * 48 + dg) = v4;
        }
        __syncthreads();   // K,V ready; everyone past previous P@V

        // S = Q'.K (packed over col pairs)
        u64 s2[4][2];
#pragma unroll
        for (int i = 0; i < 4; i++) { s2[i][0] = 0ull; s2[i][1] = 0ull; }
#pragma unroll 8
        for (int d = 0; d < DIMP; d++) {
            float4 q4 = *(const float4*)(Qs + d * 68 + rs);
            ulonglong2 kk = *(const ulonglong2*)(Ks + d * 68 + cs);
            u64 qb0 = bc2(q4.x), qb1 = bc2(q4.y), qb2 = bc2(q4.z), qb3 = bc2(q4.w);
            fma2(s2[0][0], qb0, kk.x); fma2(s2[0][1], qb0, kk.y);
            fma2(s2[1][0], qb1, kk.x); fma2(s2[1][1], qb1, kk.y);
            fma2(s2[2][0], qb2, kk.x); fma2(s2[2][1], qb2, kk.y);
            fma2(s2[3][0], qb3, kk.x); fma2(s2[3][1], qb3, kk.y);
        }

        // add column bias kb
        {
            float4 kb4 = *(const float4*)(kbg + j0 + cs);
            u64 kx = pk2(kb4.x, kb4.y), ky = pk2(kb4.z, kb4.w);
#pragma unroll
            for (int i = 0; i < 4; i++) { add2(s2[i][0], kx); add2(s2[i][1], ky); }
        }

        // unpack + mask
        float s[4][4];
#pragma unroll
        for (int i = 0; i < 4; i++) {
            upk2(s2[i][0], s[i][0], s[i][1]);
            upk2(s2[i][1], s[i][2], s[i][3]);
            const unsigned char* mp =
                mask + ((size_t)b * NSEQ + (i0 + rs + i)) * NSEQ + j0 + cs;
            uchar4 mv = *(const uchar4*)mp;
            if (mv.x) s[i][0] = -INFINITY;
            if (mv.y) s[i][1] = -INFINITY;
            if (mv.z) s[i][2] = -INFINITY;
            if (mv.w) s[i][3] = -INFINITY;
        }

        // register stats via half-warp shuffles
        float fac[4];
#pragma unroll
        for (int i = 0; i < 4; i++) {
            float mx = fmaxf(fmaxf(s[i][0], s[i][1]), fmaxf(s[i][2], s[i][3]));
            mx = fmaxf(mx, __shfl_xor_sync(0xffffffffu, mx, 1));
            mx = fmaxf(mx, __shfl_xor_sync(0xffffffffu, mx, 2));
            mx = fmaxf(mx, __shfl_xor_sync(0xffffffffu, mx, 4));
            mx = fmaxf(mx, __shfl_xor_sync(0xffffffffu, mx, 8));
            float mn = fmaxf(mrow[i], mx);
            fac[i] = (mrow[i] == -INFINITY) ? 0.f : __expf(mrow[i] - mn);
            mrow[i] = mn;
            float p0 = __expf(s[i][0] - mn);
            float p1 = __expf(s[i][1] - mn);
            float p2 = __expf(s[i][2] - mn);
            float p3 = __expf(s[i][3] - mn);
            if (mn == -INFINITY) { p0 = p1 = p2 = p3 = 0.f; }
            s[i][0] = p0; s[i][1] = p1; s[i][2] = p2; s[i][3] = p3;
            float sum = (p0 + p1) + (p2 + p3);
            sum += __shfl_xor_sync(0xffffffffu, sum, 1);
            sum += __shfl_xor_sync(0xffffffffu, sum, 2);
            sum += __shfl_xor_sync(0xffffffffu, sum, 4);
            sum += __shfl_xor_sync(0xffffffffu, sum, 8);
            lrow[i] = lrow[i] * fac[i] + sum;
        }

        // write exp'd P transposed (col-major): Ps[col][row], float4 over rows
#pragma unroll
        for (int c = 0; c < 4; c++) {
            float4 pv = make_float4(s[0][c], s[1][c], s[2][c], s[3][c]);
            *(float4*)(Ps + (cs + c) * 68 + rs) = pv;
        }
        __syncthreads();   // Ps complete

        // rescale acc + O += P @ V
        {
            u64 f0 = pk2(fac[0], fac[1]);
            u64 f1 = pk2(fac[2], fac[3]);
#pragma unroll
            for (int j = 0; j < 3; j++) { mul2(acc2[0][j], f0); mul2(acc2[1][j], f1); }
        }
#pragma unroll 4
        for (int j = 0; j < 64; j++) {
            ulonglong2 pp = *(const ulonglong2*)(Ps + j * 68 + rs);
            const float* vr = Vs + j * 48 + c0v;
            u64 vb0 = bc2(vr[0]), vb1 = bc2(vr[1]), vb2 = bc2(vr[2]);
            fma2(acc2[0][0], pp.x, vb0); fma2(acc2[1][0], pp.y, vb0);
            fma2(acc2[0][1], pp.x, vb1); fma2(acc2[1][1], pp.y, vb1);
            fma2(acc2[0][2], pp.x, vb2); fma2(acc2[1][2], pp.y, vb2);
        }
    }

    // normalize and write ctx
    float accf[4][3];
#pragma unroll
    for (int j = 0; j < 3; j++) {
        upk2(acc2[0][j], accf[0][j], accf[1][j]);
        upk2(acc2[1][j], accf[2][j], accf[3][j]);
    }
#pragma unroll
    for (int ri = 0; ri < 4; ri++) {
        int irow = rs + ri;
        float inv = 1.f / lrow[ri];
        size_t ob = ((size_t)b * NSEQ + (i0 + irow)) * CTXW;
#pragma unroll
        for (int ci = 0; ci < 3; ci++) {
            int c = c0v + ci;
            if (c >= DIMT) continue;
            float o = accf[ri][ci] * inv;
            if (c < HD)
                ctx[ob + h * HD + c] = o;
            else
                ctx[ob + 256 + h * PDIM + (c - HD)] = o;
        }
    }
}

// ---------------------------------------------------------------------------
extern "C" void kernel_launch(void* const* d_in, const int* in_sizes, int n_in,
                              void* d_out, int out_size) {
    const float* feat   = (const float*)d_in[0];
    const float* coords = (const float*)d_in[1];
    const unsigned char* mask = (const unsigned char*)d_in[2];
    const float* Wq  = (const float*)d_in[3];
    const float* bq  = (const float*)d_in[4];
    const float* Wk  = (const float*)d_in[5];
    const float* bk  = (const float*)d_in[6];
    const float* Wv  = (const float*)d_in[7];
    const float* bv  = (const float*)d_in[8];
    const float* Wqp = (const float*)d_in[9];
    const float* bqp = (const float*)d_in[10];
    const float* Wkp = (const float*)d_in[11];
    const float* bkp = (const float*)d_in[12];
    const float* Wvp = (const float*)d_in[13];
    const float* bvp = (const float*)d_in[14];
    const float* Wo  = (const float*)d_in[15];
    const float* bo  = (const float*)d_in[16];
    const float* w_c = (const float*)d_in[17];
    const float* w_l = (const float*)d_in[18];
    float* out = (float*)d_out;

    void* p;
    cudaGetSymbolAddress(&p, g_praw);  float* praw = (float*)p;
    cudaGetSymbolAddress(&p, g_ctx);   float* ctx  = (float*)p;

    const int M = BSZ * NSEQ;   // 4096

    ProjArgs pa;
    pa.W[0] = Wq;  pa.bias[0] = bq;
    pa.W[1] = Wk;  pa.bias[1] = bk;
    pa.W[2] = Wv;  pa.bias[2] = bv;
    pa.W[3] = Wqp; pa.bias[3] = bqp;
    pa.W[4] = Wkp; pa.bias[4] = bkp;
    pa.W[5] = Wvp; pa.bias[5] = bvp;
    proj_kernel<<<dim3(18, M / 64), 256>>>(feat, pa, praw);

    transform_kernel<<<M, 128>>>(coords, w_c, w_l);

    cudaFuncSetAttribute(attn_kernel, cudaFuncAttributeMaxDynamicSharedMemorySize,
                         ATT_SMEM * (int)sizeof(float));
    attn_kernel<<<dim3(NSEQ / 64, HN, BSZ), 256, ATT_SMEM * (int)sizeof(float)>>>(mask, ctx);

    gemm_kernel<<<dim3(4, M / 64), 256>>>(ctx, Wo, bo, out, CTXW, 256, 256);
}

// round 4
// speedup vs baseline: 1.2593x; 1.0546x over previous
#include <cuda_runtime.h>
#include <math.h>

// Problem constants
#define BSZ   2
#define NSEQ  2048
#define HN    8
#define HD    32
#define EMB   256
#define PDIM  12          // QP*3
#define DIMT  44          // 32 + 12
#define DIMP  48          // padded
#define NRAW  1056        // 256*3 + 96*3
#define CTXW  352         // 256 + 96

typedef unsigned long long u64;

// ---- packed fp32x2 helpers (FFMA2: ptxas never emits from C++) ----
__device__ __forceinline__ u64 pk2(float lo, float hi) {
    u64 r; asm("mov.b64 %0, {%1, %2};" : "=l"(r) : "f"(lo), "f"(hi)); return r;
}
__device__ __forceinline__ u64 bc2(float x) { return pk2(x, x); }
__device__ __forceinline__ void fma2(u64& d, u64 a, u64 b) {
    asm("fma.rn.f32x2 %0, %1, %2, %0;" : "+l"(d) : "l"(a), "l"(b));
}
__device__ __forceinline__ void add2(u64& d, u64 a) {
    asm("add.rn.f32x2 %0, %0, %1;" : "+l"(d) : "l"(a));
}
__device__ __forceinline__ void mul2(u64& d, u64 a) {
    asm("mul.rn.f32x2 %0, %0, %1;" : "+l"(d) : "l"(a));
}
__device__ __forceinline__ void upk2(u64 v, float& lo, float& hi) {
    asm("mov.b64 {%0, %1}, %2;" : "=f"(lo), "=f"(hi) : "l"(v));
}

// Scratch (device globals; allocation-free rule)
__device__ float g_praw[BSZ * NSEQ * NRAW];
__device__ float g_q[BSZ * HN * NSEQ * DIMP];
__device__ float g_k[BSZ * HN * NSEQ * DIMP];
__device__ float g_v[BSZ * HN * NSEQ * DIMP];
__device__ float g_kb[BSZ * HN * NSEQ];
__device__ float g_ctx[BSZ * NSEQ * CTXW];

// ---------------------------------------------------------------------------
// Shared GEMM tile body: C[m, coff+n] = A[m,:K256] @ W[:,n] + bias[n]
// BM=64, BN=64, BK=16, 256 threads, 4x4 tile via FFMA2.
// ---------------------------------------------------------------------------
__device__ __forceinline__
void gemm_body(const float* __restrict__ A, const float* __restrict__ W,
               const float* __restrict__ bias, float* __restrict__ C,
               int K, int Nw, int ldc, int coff, int m0, int n0) {
    __shared__ float As[16][68];
    __shared__ float Bs[16][68];
    const int t = threadIdx.x;
    const int arow = t >> 2;
    const int akg  = (t & 3) * 4;
    const int bk   = t >> 4;
    const int bn   = (t & 15) * 4;
    const int cx = (t & 15) * 4;
    const int ry = (t >> 4) * 4;

    u64 acc2[4][2];
#pragma unroll
    for (int i = 0; i < 4; i++) { acc2[i][0] = 0ull; acc2[i][1] = 0ull; }

    for (int k0 = 0; k0 < K; k0 += 16) {
        float4 a4 = *(const float4*)(A + (size_t)(m0 + arow) * K + k0 + akg);
        As[akg + 0][arow] = a4.x;
        As[akg + 1][arow] = a4.y;
        As[akg + 2][arow] = a4.z;
        As[akg + 3][arow] = a4.w;
        {
            const float* wr = W + (size_t)(k0 + bk) * Nw;
            int gcol = n0 + bn;
            if (gcol + 3 < Nw) {
                float4 b4 = *(const float4*)(wr + gcol);
                Bs[bk][bn + 0] = b4.x;
                Bs[bk][bn + 1] = b4.y;
                Bs[bk][bn + 2] = b4.z;
                Bs[bk][bn + 3] = b4.w;
            } else {
#pragma unroll
                for (int i = 0; i < 4; i++)
                    Bs[bk][bn + i] = (gcol + i < Nw) ? wr[gcol + i] : 0.f;
            }
        }
        __syncthreads();
#pragma unroll
        for (int kk = 0; kk < 16; kk++) {
            float4 av = *(const float4*)&As[kk][ry];
            ulonglong2 bv = *(const ulonglong2*)&Bs[kk][cx];
            u64 ab0 = bc2(av.x), ab1 = bc2(av.y), ab2 = bc2(av.z), ab3 = bc2(av.w);
            fma2(acc2[0][0], ab0, bv.x); fma2(acc2[0][1], ab0, bv.y);
            fma2(acc2[1][0], ab1, bv.x); fma2(acc2[1][1], ab1, bv.y);
            fma2(acc2[2][0], ab2, bv.x); fma2(acc2[2][1], ab2, bv.y);
            fma2(acc2[3][0], ab3, bv.x); fma2(acc2[3][1], ab3, bv.y);
        }
        __syncthreads();
    }
#pragma unroll
    for (int i = 0; i < 4; i++) {
        float c0, c1, c2, c3;
        upk2(acc2[i][0], c0, c1);
        upk2(acc2[i][1], c2, c3);
        float cc[4] = {c0, c1, c2, c3};
        float* crow = C + (size_t)(m0 + ry + i) * ldc + coff;
#pragma unroll
        for (int j = 0; j < 4; j++) {
            int col = n0 + cx + j;
            if (col < Nw) crow[col] = cc[j] + bias[col];
        }
    }
}

// Merged projection GEMM: 6 matrices in one launch.
struct ProjArgs {
    const float* W[6];
    const float* bias[6];
};

__global__ __launch_bounds__(256)
void proj_kernel(const float* __restrict__ A, ProjArgs pa, float* __restrict__ C) {
    // tiles per matrix: 4,4,4,2,2,2 (Nw 256,256,256,96,96,96)
    const int bx = blockIdx.x;
    int g, n0;
    if (bx < 12) { g = bx >> 2; n0 = (bx & 3) * 64; }
    else         { g = 3 + ((bx - 12) >> 1); n0 = ((bx - 12) & 1) * 64; }
    const int nw   = (g < 3) ? 256 : 96;
    const int coff = (g < 3) ? g * 256 : 768 + (g - 3) * 96;
    gemm_body(A, pa.W[g], pa.bias[g], C, EMB, nw, NRAW, coff, blockIdx.y * 64, n0);
}

__global__ __launch_bounds__(256)
void gemm_kernel(const float* __restrict__ A, const float* __restrict__ W,
                 const float* __restrict__ bias, float* __restrict__ C,
                 int K, int Nw, int ldc) {
    gemm_body(A, W, bias, C, K, Nw, ldc, 0, blockIdx.y * 64, blockIdx.x * 64);
}

// ---------------------------------------------------------------------------
// Transform: build scaled/padded Q,K,V (layout [b][h][pos][48]) + kb bias.
// ---------------------------------------------------------------------------
__device__ __forceinline__ float softplusf(float x) {
    return (x > 20.f) ? x : log1pf(expf(x));
}

__global__ __launch_bounds__(128)
void transform_kernel(const float* __restrict__ coords,
                      const float* __restrict__ w_c,
                      const float* __restrict__ w_l) {
    __shared__ float row[NRAW];
    __shared__ float c3[3];
    __shared__ float wl[HN], wc[HN];
    const int blk = blockIdx.x;
    const int b = blk >> 11;
    const int pos = blk & (NSEQ - 1);
    const int t = threadIdx.x;

    for (int i = t; i < NRAW; i += 128) row[i] = g_praw[(size_t)blk * NRAW + i];
    if (t < 3) c3[t] = coords[(size_t)blk * 3 + t];
    if (t < HN) { wl[t] = softplusf(w_l[t]); wc[t] = softplusf(w_c[t]); }
    __syncthreads();

    if (t < HN) {
        int h = t;
        float s = 0.f;
#pragma unroll
        for (int e = 0; e < PDIM; e++) {
            float v = row[864 + h * PDIM + e] + c3[e % 3];
            s = fmaf(v, v, s);
        }
        g_kb[((size_t)(b * HN + h)) * NSEQ + pos] = -0.5f * wc[h] * s;
    }

    const float RS32 = 0.17677669529663688f;
    for (int idx = t; idx < HN * DIMP; idx += 128) {
        int h = idx / DIMP, d = idx % DIMP;
        size_t o = (((size_t)(b * HN + h)) * NSEQ + pos) * DIMP + d;
        float qv, kv, vv;
        if (d < HD) {
            qv = row[h * HD + d] * (wl[h] * RS32);
            kv = row[256 + h * HD + d];
            vv = row[512 + h * HD + d];
        } else if (d < DIMT) {
            int e = d - HD;
            float cc = c3[e % 3];
            qv = (row[768 + h * PDIM + e] + cc) * wc[h];
            kv = row[864 + h * PDIM + e] + cc;
            vv = row[960 + h * PDIM + e] + cc;
        } else {
            qv = kv = vv = 0.f;
        }
        g_q[o] = qv; g_k[o] = kv; g_v[o] = vv;
    }
}

// ---------------------------------------------------------------------------
// Attention: flash online softmax; register stats via half-warp shuffles;
// double-buffered V; 2 syncthreads/tile.
// Row groups owned by half-warps: rs=(t>>4)*4; S cols cs=(t&15)*4.
// ---------------------------------------------------------------------------
#define ATT_SMEM ((48*68) + (48*68) + 2*(64*48) + (64*68))   // 17024 floats

__global__ __launch_bounds__(256, 3)
void attn_kernel(const unsigned char* __restrict__ mask, float* __restrict__ ctx) {
    extern __shared__ float sm[];
    float* Qs  = sm;                 // [48][68] transposed
    float* Ks  = Qs + 48 * 68;       // [48][68] transposed
    float* Vb0 = Ks + 48 * 68;       // [64][48]
    float* Vb1 = Vb0 + 64 * 48;      // [64][48]
    float* Ps  = Vb1 + 64 * 48;      // [64 cols][68] (col-major, exp'd P)

    const int i0 = blockIdx.x * 64;
    const int h = blockIdx.y;
    const int b = blockIdx.z;
    const int bh = b * HN + h;
    const float* Qg = g_q + (size_t)bh * NSEQ * DIMP;
    const float* Kg = g_k + (size_t)bh * NSEQ * DIMP;
    const float* Vg = g_v + (size_t)bh * NSEQ * DIMP;
    const float* kbg = g_kb + (size_t)bh * NSEQ;

    const int t = threadIdx.x;
    const int rs  = (t >> 4) * 4;   // 4 rows (half-warp shared)
    const int cs  = (t & 15) * 4;   // 4 S-cols
    const int c0v = (t & 15) * 3;   // 3 V-cols

    // load Q tile transposed
    for (int idx = t; idx < 64 * 12; idx += 256) {
        int r = idx / 12, dg = (idx % 12) * 4;
        float4 q4 = *(const float4*)(Qg + (size_t)(i0 + r) * DIMP + dg);
        Qs[(dg + 0) * 68 + r] = q4.x;
        Qs[(dg + 1) * 68 + r] = q4.y;
        Qs[(dg + 2) * 68 + r] = q4.z;
        Qs[(dg + 3) * 68 + r] = q4.w;
    }

    float mrow[4], lrow[4];
#pragma unroll
    for (int i = 0; i < 4; i++) { mrow[i] = -INFINITY; lrow[i] = 0.f; }
    u64 acc2[2][3];
#pragma unroll
    for (int i = 0; i < 2; i++)
#pragma unroll
        for (int j = 0; j < 3; j++) acc2[i][j] = 0ull;

    int buf = 0;
    for (int j0 = 0; j0 < NSEQ; j0 += 64, buf ^= 1) {
        float* Vs = buf ? Vb1 : Vb0;
        // load K transposed + V
        for (int idx = t; idx < 64 * 12; idx += 256) {
            int r = idx / 12, dg = (idx % 12) * 4;
            float4 k4 = *(const float4*)(Kg + (size_t)(j0 + r) * DIMP + dg);
            Ks[(dg + 0) * 68 + r] = k4.x;
            Ks[(dg + 1) * 68 + r] = k4.y;
            Ks[(dg + 2) * 68 + r] = k4.z;
            Ks[(dg + 3) * 68 + r] = k4.w;
            float4 v4 = *(const float4*)(Vg + (size_t)(j0 + r) * DIMP + dg);
            *(float4*)(Vs + r * 48 + dg) = v4;
        }
        __syncthreads();   // K,V ready; everyone past previous P@V

        // S = Q'.K (packed over col pairs)
        u64 s2[4][2];
#pragma unroll
        for (int i = 0; i < 4; i++) { s2[i][0] = 0ull; s2[i][1] = 0ull; }
#pragma unroll 8
        for (int d = 0; d < DIMP; d++) {
            float4 q4 = *(const float4*)(Qs + d * 68 + rs);
            ulonglong2 kk = *(const ulonglong2*)(Ks + d * 68 + cs);
            u64 qb0 = bc2(q4.x), qb1 = bc2(q4.y), qb2 = bc2(q4.z), qb3 = bc2(q4.w);
            fma2(s2[0][0], qb0, kk.x); fma2(s2[0][1], qb0, kk.y);
            fma2(s2[1][0], qb1, kk.x); fma2(s2[1][1], qb1, kk.y);
            fma2(s2[2][0], qb2, kk.x); fma2(s2[2][1], qb2, kk.y);
            fma2(s2[3][0], qb3, kk.x); fma2(s2[3][1], qb3, kk.y);
        }

        // add column bias kb
        {
            float4 kb4 = *(const float4*)(kbg + j0 + cs);
            u64 kx = pk2(kb4.x, kb4.y), ky = pk2(kb4.z, kb4.w);
#pragma unroll
            for (int i = 0; i < 4; i++) { add2(s2[i][0], kx); add2(s2[i][1], ky); }
        }

        // unpack + mask
        float s[4][4];
#pragma unroll
        for (int i = 0; i < 4; i++) {
            upk2(s2[i][0], s[i][0], s[i][1]);
            upk2(s2[i][1], s[i][2], s[i][3]);
            const unsigned char* mp =
                mask + ((size_t)b * NSEQ + (i0 + rs + i)) * NSEQ + j0 + cs;
            uchar4 mv = *(const uchar4*)mp;
            if (mv.x) s[i][0] = -INFINITY;
            if (mv.y) s[i][1] = -INFINITY;
            if (mv.z) s[i][2] = -INFINITY;
            if (mv.w) s[i][3] = -INFINITY;
        }

        // register stats via half-warp shuffles
        float fac[4];
#pragma unroll
        for (int i = 0; i < 4; i++) {
            float mx = fmaxf(fmaxf(s[i][0], s[i][1]), fmaxf(s[i][2], s[i][3]));
            mx = fmaxf(mx, __shfl_xor_sync(0xffffffffu, mx, 1));
            mx = fmaxf(mx, __shfl_xor_sync(0xffffffffu, mx, 2));
            mx = fmaxf(mx, __shfl_xor_sync(0xffffffffu, mx, 4));
            mx = fmaxf(mx, __shfl_xor_sync(0xffffffffu, mx, 8));
            float mn = fmaxf(mrow[i], mx);
            fac[i] = (mrow[i] == -INFINITY) ? 0.f : __expf(mrow[i] - mn);
            mrow[i] = mn;
            float p0 = __expf(s[i][0] - mn);
            float p1 = __expf(s[i][1] - mn);
            float p2 = __expf(s[i][2] - mn);
            float p3 = __expf(s[i][3] - mn);
            if (mn == -INFINITY) { p0 = p1 = p2 = p3 = 0.f; }
            s[i][0] = p0; s[i][1] = p1; s[i][2] = p2; s[i][3] = p3;
            float sum = (p0 + p1) + (p2 + p3);
            sum += __shfl_xor_sync(0xffffffffu, sum, 1);
            sum += __shfl_xor_sync(0xffffffffu, sum, 2);
            sum += __shfl_xor_sync(0xffffffffu, sum, 4);
            sum += __shfl_xor_sync(0xffffffffu, sum, 8);
            lrow[i] = lrow[i] * fac[i] + sum;
        }

        // write exp'd P transposed (col-major): Ps[col][row], float4 over rows
#pragma unroll
        for (int c = 0; c < 4; c++) {
            float4 pv = make_float4(s[0][c], s[1][c], s[2][c], s[3][c]);
            *(float4*)(Ps + (cs + c) * 68 + rs) = pv;
        }
        __syncthreads();   // Ps complete

        // rescale acc + O += P @ V
        {
            u64 f0 = pk2(fac[0], fac[1]);
            u64 f1 = pk2(fac[2], fac[3]);
#pragma unroll
            for (int j = 0; j < 3; j++) { mul2(acc2[0][j], f0); mul2(acc2[1][j], f1); }
        }
#pragma unroll 4
        for (int j = 0; j < 64; j++) {
            ulonglong2 pp = *(const ulonglong2*)(Ps + j * 68 + rs);
            const float* vr = Vs + j * 48 + c0v;
            u64 vb0 = bc2(vr[0]), vb1 = bc2(vr[1]), vb2 = bc2(vr[2]);
            fma2(acc2[0][0], pp.x, vb0); fma2(acc2[1][0], pp.y, vb0);
            fma2(acc2[0][1], pp.x, vb1); fma2(acc2[1][1], pp.y, vb1);
            fma2(acc2[0][2], pp.x, vb2); fma2(acc2[1][2], pp.y, vb2);
        }
    }

    // normalize and write ctx
    float accf[4][3];
#pragma unroll
    for (int j = 0; j < 3; j++) {
        upk2(acc2[0][j], accf[0][j], accf[1][j]);
        upk2(acc2[1][j], accf[2][j], accf[3][j]);
    }
#pragma unroll
    for (int ri = 0; ri < 4; ri++) {
        int irow = rs + ri;
        float inv = 1.f / lrow[ri];
        size_t ob = ((size_t)b * NSEQ + (i0 + irow)) * CTXW;
#pragma unroll
        for (int ci = 0; ci < 3; ci++) {
            int c = c0v + ci;
            if (c >= DIMT) continue;
            float o = accf[ri][ci] * inv;
            if (c < HD)
                ctx[ob + h * HD + c] = o;
            else
                ctx[ob + 256 + h * PDIM + (c - HD)] = o;
        }
    }
}

// ---------------------------------------------------------------------------
extern "C" void kernel_launch(void* const* d_in, const int* in_sizes, int n_in,
                              void* d_out, int out_size) {
    const float* feat   = (const float*)d_in[0];
    const float* coords = (const float*)d_in[1];
    const unsigned char* mask = (const unsigned char*)d_in[2];
    const float* Wq  = (const float*)d_in[3];
    const float* bq  = (const float*)d_in[4];
    const float* Wk  = (const float*)d_in[5];
    const float* bk  = (const float*)d_in[6];
    const float* Wv  = (const float*)d_in[7];
    const float* bv  = (const float*)d_in[8];
    const float* Wqp = (const float*)d_in[9];
    const float* bqp = (const float*)d_in[10];
    const float* Wkp = (const float*)d_in[11];
    const float* bkp = (const float*)d_in[12];
    const float* Wvp = (const float*)d_in[13];
    const float* bvp = (const float*)d_in[14];
    const float* Wo  = (const float*)d_in[15];
    const float* bo  = (const float*)d_in[16];
    const float* w_c = (const float*)d_in[17];
    const float* w_l = (const float*)d_in[18];
    float* out = (float*)d_out;

    void* p;
    cudaGetSymbolAddress(&p, g_praw);  float* praw = (float*)p;
    cudaGetSymbolAddress(&p, g_ctx);   float* ctx  = (float*)p;

    const int M = BSZ * NSEQ;   // 4096

    ProjArgs pa;
    pa.W[0] = Wq;  pa.bias[0] = bq;
    pa.W[1] = Wk;  pa.bias[1] = bk;
    pa.W[2] = Wv;  pa.bias[2] = bv;
    pa.W[3] = Wqp; pa.bias[3] = bqp;
    pa.W[4] = Wkp; pa.bias[4] = bkp;
    pa.W[5] = Wvp; pa.bias[5] = bvp;
    proj_kernel<<<dim3(18, M / 64), 256>>>(feat, pa, praw);

    transform_kernel<<<M, 128>>>(coords, w_c, w_l);

    cudaFuncSetAttribute(attn_kernel, cudaFuncAttributeMaxDynamicSharedMemorySize,
                         ATT_SMEM * (int)sizeof(float));
    attn_kernel<<<dim3(NSEQ / 64, HN, BSZ), 256, ATT_SMEM * (int)sizeof(float)>>>(mask, ctx);

    gemm_kernel<<<dim3(4, M / 64), 256>>>(ctx, Wo, bo, out, CTXW, 256, 256);
}

// round 6
// speedup vs baseline: 1.7371x; 1.3793x over previous
#include <cuda_runtime.h>
#include <cuda_bf16.h>
#include <mma.h>
#include <math.h>
using namespace nvcuda;

#define BSZ 2
#define NSEQ 2048
#define HN 8
#define HD 32
#define EMB 256
#define PDIM 12
#define DIMT 44
#define NRAW 1056
#define CTXW 352
#define NBH 16

typedef unsigned long long u64;
typedef unsigned int u32;

// ---- packed fp32x2 (GEMMs) ----
__device__ __forceinline__ u64 pk2(float lo, float hi) {
    u64 r; asm("mov.b64 %0, {%1, %2};" : "=l"(r) : "f"(lo), "f"(hi)); return r;
}
__device__ __forceinline__ u64 bc2(float x) { return pk2(x, x); }
__device__ __forceinline__ void fma2(u64& d, u64 a, u64 b) {
    asm("fma.rn.f32x2 %0, %1, %2, %0;" : "+l"(d) : "l"(a), "l"(b));
}
__device__ __forceinline__ void upk2(u64 v, float& lo, float& hi) {
    asm("mov.b64 {%0, %1}, %2;" : "=f"(lo), "=f"(hi) : "l"(v));
}

// Scratch (allocation-free rule)
__device__ float g_praw[BSZ * NSEQ * NRAW];
__device__ float g_kb[NBH * NSEQ];
__device__ float g_ctx[BSZ * NSEQ * CTXW];
__device__ __nv_bfloat16 g_qh[NBH * NSEQ * 64];
__device__ __nv_bfloat16 g_ql[NBH * NSEQ * 64];
__device__ __nv_bfloat16 g_kh[NBH * NSEQ * 64];
__device__ __nv_bfloat16 g_kl[NBH * NSEQ * 64];
__device__ __nv_bfloat16 g_vh[NBH * NSEQ * 64];
__device__ __nv_bfloat16 g_vl[NBH * NSEQ * 64];

// ---------------- GEMM (FFMA2) ----------------
__device__ __forceinline__
void gemm_body(const float* __restrict__ A, const float* __restrict__ W,
               const float* __restrict__ bias, float* __restrict__ C,
               int K, int Nw, int ldc, int coff, int m0, int n0) {
    __shared__ float As[16][68];
    __shared__ float Bs[16][68];
    const int t = threadIdx.x;
    const int arow = t >> 2, akg = (t & 3) * 4, bk = t >> 4, bn = (t & 15) * 4;
    const int cx = (t & 15) * 4, ry = (t >> 4) * 4;
    u64 acc2[4][2];
#pragma unroll
    for (int i = 0; i < 4; i++) { acc2[i][0] = 0ull; acc2[i][1] = 0ull; }
    for (int k0 = 0; k0 < K; k0 += 16) {
        float4 a4 = *(const float4*)(A + (size_t)(m0 + arow) * K + k0 + akg);
        As[akg + 0][arow] = a4.x; As[akg + 1][arow] = a4.y;
        As[akg + 2][arow] = a4.z; As[akg + 3][arow] = a4.w;
        const float* wr = W + (size_t)(k0 + bk) * Nw;
        int gcol = n0 + bn;
        if (gcol + 3 < Nw) {
            float4 b4 = *(const float4*)(wr + gcol);
            Bs[bk][bn] = b4.x; Bs[bk][bn + 1] = b4.y; Bs[bk][bn + 2] = b4.z; Bs[bk][bn + 3] = b4.w;
        } else {
#pragma unroll
            for (int i = 0; i < 4; i++) Bs[bk][bn + i] = (gcol + i < Nw) ? wr[gcol + i] : 0.f;
        }
        __syncthreads();
#pragma unroll
        for (int kk = 0; kk < 16; kk++) {
            float4 av = *(const float4*)&As[kk][ry];
            ulonglong2 bv = *(const ulonglong2*)&Bs[kk][cx];
            u64 a0 = bc2(av.x), a1 = bc2(av.y), a2 = bc2(av.z), a3 = bc2(av.w);
            fma2(acc2[0][0], a0, bv.x); fma2(acc2[0][1], a0, bv.y);
            fma2(acc2[1][0], a1, bv.x); fma2(acc2[1][1], a1, bv.y);
            fma2(acc2[2][0], a2, bv.x); fma2(acc2[2][1], a2, bv.y);
            fma2(acc2[3][0], a3, bv.x); fma2(acc2[3][1], a3, bv.y);
        }
        __syncthreads();
    }
#pragma unroll
    for (int i = 0; i < 4; i++) {
        float c0, c1, c2, c3;
        upk2(acc2[i][0], c0, c1); upk2(acc2[i][1], c2, c3);
        float cc[4] = {c0, c1, c2, c3};
        float* crow = C + (size_t)(m0 + ry + i) * ldc + coff;
#pragma unroll
        for (int j = 0; j < 4; j++) { int col = n0 + cx + j; if (col < Nw) crow[col] = cc[j] + bias[col]; }
    }
}

struct ProjArgs { const float* W[6]; const float* bias[6]; };

__global__ __launch_bounds__(256)
void proj_kernel(const float* __restrict__ A, ProjArgs pa, float* __restrict__ C) {
    const int bx = blockIdx.x;
    int g, n0;
    if (bx < 12) { g = bx >> 2; n0 = (bx & 3) * 64; }
    else { g = 3 + ((bx - 12) >> 1); n0 = ((bx - 12) & 1) * 64; }
    const int nw = (g < 3) ? 256 : 96;
    const int coff = (g < 3) ? g * 256 : 768 + (g - 3) * 96;
    gemm_body(A, pa.W[g], pa.bias[g], C, EMB, nw, NRAW, coff, blockIdx.y * 64, n0);
}

__global__ __launch_bounds__(256)
void gemm_kernel(const float* __restrict__ A, const float* __restrict__ W,
                 const float* __restrict__ bias, float* __restrict__ C, int K, int Nw, int ldc) {
    gemm_body(A, W, bias, C, K, Nw, ldc, 0, blockIdx.y * 64, blockIdx.x * 64);
}

// ---------------- Transform: bf16 hi/lo split ----------------
__device__ __forceinline__ float softplusf(float x) { return (x > 20.f) ? x : log1pf(expf(x)); }

__global__ __launch_bounds__(128)
void transform_kernel(const float* __restrict__ coords, const float* __restrict__ w_c,
                      const float* __restrict__ w_l) {
    __shared__ float row[NRAW];
    __shared__ float c3[3];
    __shared__ float wl[HN], wc[HN];
    const int blk = blockIdx.x, b = blk >> 11, pos = blk & (NSEQ - 1);
    const int t = threadIdx.x;
    for (int i = t; i < NRAW; i += 128) row[i] = g_praw[(size_t)blk * NRAW + i];
    if (t < 3) c3[t] = coords[(size_t)blk * 3 + t];
    if (t < HN) { wl[t] = softplusf(w_l[t]); wc[t] = softplusf(w_c[t]); }
    __syncthreads();

    if (t < HN) {
        float s = 0.f;
#pragma unroll
        for (int e = 0; e < PDIM; e++) {
            float v = row[864 + t * PDIM + e] + c3[e % 3];
            s = fmaf(v, v, s);
        }
        g_kb[((size_t)(b * HN + t)) * NSEQ + pos] = -0.5f * wc[t] * s;
    }

    const float RS32 = 0.17677669529663688f;
    for (int idx = t; idx < HN * 48; idx += 128) {
        int h = idx / 48, d = idx % 48;
        float qv = 0.f, kv = 0.f, vv = 0.f;
        if (d < HD) {
            qv = row[h * HD + d] * (wl[h] * RS32);
            kv = row[256 + h * HD + d];
            vv = row[512 + h * HD + d];
        } else if (d < DIMT) {
            int e = d - HD;
            float cc = c3[e % 3];
            qv = (row[768 + h * PDIM + e] + cc) * wc[h];
            kv = row[864 + h * PDIM + e] + cc;
            vv = row[960 + h * PDIM + e] + cc;
        }
        size_t o = ((size_t)(b * HN + h) * NSEQ + pos) * 64 + d;
        __nv_bfloat16 qh = __float2bfloat16(qv);
        __nv_bfloat16 kh = __float2bfloat16(kv);
        __nv_bfloat16 vh = __float2bfloat16(vv);
        g_qh[o] = qh; g_ql[o] = __float2bfloat16(qv - __bfloat162float(qh));
        g_kh[o] = kh; g_kl[o] = __float2bfloat16(kv - __bfloat162float(kh));
        g_vh[o] = vh; g_vl[o] = __float2bfloat16(vv - __bfloat162float(vh));
    }
}

// ---------------- wmma (HMMA) flash attention ----------------
// smem byte offsets
#define SB_QH 0
#define SB_QL 12288
#define SB_KH 24576
#define SB_KL 30720
#define SB_VH 36864
#define SB_VL 43008
#define SB_S  49152          // f32 [128][80]; aliases Ph/Pl
#define SB_PH 49152          // bf16 [128][80]
#define SB_PL 69632          // bf16 [128][80]
#define SB_TOT 90112

__global__ __launch_bounds__(256, 2)
void attn_kernel(const unsigned char* __restrict__ mask, float* __restrict__ ctx) {
    extern __shared__ char smem[];
    __nv_bfloat16* Qh = (__nv_bfloat16*)(smem + SB_QH);
    __nv_bfloat16* Ql = (__nv_bfloat16*)(smem + SB_QL);
    __nv_bfloat16* Kh = (__nv_bfloat16*)(smem + SB_KH);
    __nv_bfloat16* Kl = (__nv_bfloat16*)(smem + SB_KL);
    __nv_bfloat16* Vh = (__nv_bfloat16*)(smem + SB_VH);
    __nv_bfloat16* Vl = (__nv_bfloat16*)(smem + SB_VL);
    float* Ss = (float*)(smem + SB_S);
    __nv_bfloat16* Ph = (__nv_bfloat16*)(smem + SB_PH);
    __nv_bfloat16* Pl = (__nv_bfloat16*)(smem + SB_PL);

    const int t = threadIdx.x;
    const int w = t >> 5;
    const int rb = w * 16;               // warp's row block
    const int myrow = t >> 1, half = t & 1;
    const int i0 = blockIdx.x * 128, h = blockIdx.y, b = blockIdx.z;
    const int bh = b * HN + h;
    const float* kbg = g_kb + (size_t)bh * NSEQ;

    // load Q (48 cols, ld 48)
    {
        const uint4* sh = (const uint4*)(g_qh + ((size_t)bh * NSEQ + i0) * 64);
        const uint4* sl = (const uint4*)(g_ql + ((size_t)bh * NSEQ + i0) * 64);
        for (int i = t; i < 768; i += 256) {
            int r = i / 6, g = i % 6;
            *(uint4*)(smem + SB_QH + r * 96 + g * 16) = sh[r * 8 + g];
            *(uint4*)(smem + SB_QL + r * 96 + g * 16) = sl[r * 8 + g];
        }
    }
    __syncthreads();

    wmma::fragment<wmma::matrix_a, 16, 16, 16, __nv_bfloat16, wmma::row_major> aQh[3], aQl[3];
#pragma unroll
    for (int ks = 0; ks < 3; ks++) {
        wmma::load_matrix_sync(aQh[ks], Qh + rb * 48 + ks * 16, 48);
        wmma::load_matrix_sync(aQl[ks], Ql + rb * 48 + ks * 16, 48);
    }

    wmma::fragment<wmma::accumulator, 16, 16, 16, float> oacc[3];
#pragma unroll
    for (int ct = 0; ct < 3; ct++) wmma::fill_fragment(oacc[ct], 0.f);

    float lreg = 0.f, m0 = 0.f;

    for (int tt = 0; tt < 32; tt++) {
        const int j0 = tt * 64;
        __syncthreads();                          // prev PV done (K/V/P reuse)
        {
            size_t gb = ((size_t)bh * NSEQ + j0) * 64;
            const uint4* kh = (const uint4*)(g_kh + gb);
            const uint4* kl = (const uint4*)(g_kl + gb);
            const uint4* vh = (const uint4*)(g_vh + gb);
            const uint4* vl = (const uint4*)(g_vl + gb);
            for (int i = t; i < 384; i += 256) {
                int r = i / 6, g = i % 6;
                int off = r * 96 + g * 16;
                *(uint4*)(smem + SB_KH + off) = kh[r * 8 + g];
                *(uint4*)(smem + SB_KL + off) = kl[r * 8 + g];
                *(uint4*)(smem + SB_VH + off) = vh[r * 8 + g];
                *(uint4*)(smem + SB_VL + off) = vl[r * 8 + g];
            }
        }
        __syncthreads();                          // K/V ready

        // S = Q K^T (3 splits)
#pragma unroll
        for (int jt = 0; jt < 4; jt++) {
            wmma::fragment<wmma::accumulator, 16, 16, 16, float> sacc;
            wmma::fill_fragment(sacc, 0.f);
#pragma unroll
            for (int ks = 0; ks < 3; ks++) {
                wmma::fragment<wmma::matrix_b, 16, 16, 16, __nv_bfloat16, wmma::col_major> bKh, bKl;
                wmma::load_matrix_sync(bKh, Kh + (jt * 16) * 48 + ks * 16, 48);
                wmma::load_matrix_sync(bKl, Kl + (jt * 16) * 48 + ks * 16, 48);
                wmma::mma_sync(sacc, aQh[ks], bKh, sacc);
                wmma::mma_sync(sacc, aQh[ks], bKl, sacc);
                wmma::mma_sync(sacc, aQl[ks], bKh, sacc);
            }
            wmma::store_matrix_sync(Ss + rb * 80 + jt * 16, sacc, 80, wmma::mem_row_major);
        }
        __syncthreads();                          // S ready

        // scalar: bias + mask + exp
        float s[32];
        {
            const float* srow = Ss + myrow * 80 + half * 32;
            const float* kbp = kbg + j0 + half * 32;
#pragma unroll
            for (int g = 0; g < 8; g++) {
                float4 s4 = ((const float4*)srow)[g];
                float4 k4 = ((const float4*)kbp)[g];
                s[4 * g + 0] = s4.x + k4.x; s[4 * g + 1] = s4.y + k4.y;
                s[4 * g + 2] = s4.z + k4.z; s[4 * g + 3] = s4.w + k4.w;
            }
            const u64* mp = (const u64*)(mask + ((size_t)b * NSEQ + i0 + myrow) * NSEQ + j0 + half * 32);
            u64 mw[4] = {mp[0], mp[1], mp[2], mp[3]};
#pragma unroll
            for (int c = 0; c < 32; c++)
                if ((mw[c >> 3] >> ((c & 7) * 8)) & 0xFF) s[c] = -INFINITY;
        }
        if (tt == 0) {
            float pm = -INFINITY;
#pragma unroll
            for (int c = 0; c < 32; c++) pm = fmaxf(pm, s[c]);
            pm = fmaxf(pm, __shfl_xor_sync(0xffffffffu, pm, 1));
            m0 = fmaxf(pm, -1e4f) + 2.f;
        }
        u32 phv[16], plv[16];
#pragma unroll
        for (int k = 0; k < 16; k++) {
            float p0 = __expf(s[2 * k] - m0), p1 = __expf(s[2 * k + 1] - m0);
            lreg += p0 + p1;
            __nv_bfloat162 hh = __floats2bfloat162_rn(p0, p1);
            float r0 = p0 - __bfloat162float(hh.x);
            float r1 = p1 - __bfloat162float(hh.y);
            __nv_bfloat162 ll = __floats2bfloat162_rn(r0, r1);
            phv[k] = *(u32*)&hh;
            plv[k] = *(u32*)&ll;
        }
        __syncthreads();                          // all S reads done before P overwrite
        {
            char* prh = smem + SB_PH + myrow * 160 + half * 64;
            char* prl = smem + SB_PL + myrow * 160 + half * 64;
#pragma unroll
            for (int g = 0; g < 4; g++) {
                *(uint4*)(prh + g * 16) = make_uint4(phv[4*g], phv[4*g+1], phv[4*g+2], phv[4*g+3]);
                *(uint4*)(prl + g * 16) = make_uint4(plv[4*g], plv[4*g+1], plv[4*g+2], plv[4*g+3]);
            }
        }
        __syncwarp();                             // warp w's P rows are warp-local

        // O += P V (3 splits)
#pragma unroll
        for (int kj = 0; kj < 4; kj++) {
            wmma::fragment<wmma::matrix_a, 16, 16, 16, __nv_bfloat16, wmma::row_major> pAh, pAl;
            wmma::load_matrix_sync(pAh, Ph + rb * 80 + kj * 16, 80);
            wmma::load_matrix_sync(pAl, Pl + rb * 80 + kj * 16, 80);
#pragma unroll
            for (int ct = 0; ct < 3; ct++) {
                wmma::fragment<wmma::matrix_b, 16, 16, 16, __nv_bfloat16, wmma::row_major> vBh, vBl;
                wmma::load_matrix_sync(vBh, Vh + (kj * 16) * 48 + ct * 16, 48);
                wmma::load_matrix_sync(vBl, Vl + (kj * 16) * 48 + ct * 16, 48);
                wmma::mma_sync(oacc[ct], pAh, vBh, oacc[ct]);
                wmma::mma_sync(oacc[ct], pAh, vBl, oacc[ct]);
                wmma::mma_sync(oacc[ct], pAl, vBh, oacc[ct]);
            }
        }
    }

    __syncthreads();
#pragma unroll
    for (int ct = 0; ct < 3; ct++)
        wmma::store_matrix_sync(Ss + rb * 80 + ct * 16, oacc[ct], 80, wmma::mem_row_major);
    __syncthreads();

    lreg += __shfl_xor_sync(0xffffffffu, lreg, 1);
    float inv = 1.f / lreg;
    size_t ob = ((size_t)b * NSEQ + i0 + myrow) * CTXW;
    const int cbeg = half ? 24 : 0, cend = half ? 44 : 24;
    for (int c = cbeg; c < cend; c++) {
        float o = Ss[myrow * 80 + c] * inv;
        if (c < HD) ctx[ob + h * HD + c] = o;
        else        ctx[ob + 256 + h * PDIM + (c - HD)] = o;
    }
}

// ---------------------------------------------------------------------------
extern "C" void kernel_launch(void* const* d_in, const int* in_sizes, int n_in,
                              void* d_out, int out_size) {
    const float* feat = (const float*)d_in[0];
    const float* coords = (const float*)d_in[1];
    const unsigned char* mask = (const unsigned char*)d_in[2];
    const float* Wo = (const float*)d_in[15];
    const float* bo = (const float*)d_in[16];
    float* out = (float*)d_out;

    void* p;
    cudaGetSymbolAddress(&p, g_praw); float* praw = (float*)p;
    cudaGetSymbolAddress(&p, g_ctx);  float* ctx = (float*)p;

    const int M = BSZ * NSEQ;
    ProjArgs pa;
    pa.W[0] = (const float*)d_in[3];  pa.bias[0] = (const float*)d_in[4];
    pa.W[1] = (const float*)d_in[5];  pa.bias[1] = (const float*)d_in[6];
    pa.W[2] = (const float*)d_in[7];  pa.bias[2] = (const float*)d_in[8];
    pa.W[3] = (const float*)d_in[9];  pa.bias[3] = (const float*)d_in[10];
    pa.W[4] = (const float*)d_in[11]; pa.bias[4] = (const float*)d_in[12];
    pa.W[5] = (const float*)d_in[13]; pa.bias[5] = (const float*)d_in[14];
    proj_kernel<<<dim3(18, M / 64), 256>>>(feat, pa, praw);

    transform_kernel<<<M, 128>>>(coords, (const float*)d_in[17], (const float*)d_in[18]);

    cudaFuncSetAttribute(attn_kernel, cudaFuncAttributeMaxDynamicSharedMemorySize, SB_TOT);
    attn_kernel<<<dim3(16, HN, BSZ), 256, SB_TOT>>>(mask, ctx);

    gemm_kernel<<<dim3(4, M / 64), 256>>>(ctx, Wo, bo, out, CTXW, 256, 256);
}